// round 1
// baseline (speedup 1.0000x reference)
#include <cuda_runtime.h>
#include <math.h>
#include <stdint.h>

#define NN 8192
#define FIN 256
#define FOUT 64
#define LRALPHA 0.2f

#define BM 64
#define BK 64
#define BN 80          // 64 out cols + 1 ones(denominator) + 15 pad
#define WH_STRIDE 80

// persistent scratch (no allocations allowed)
__device__ __align__(16) float g_Whext[NN * WH_STRIDE];  // ~2.6 MB
__device__ float g_f1[NN];
__device__ float g_f2[NN];
__device__ float g_P[NN];   // exp(f1)
__device__ float g_Q[NN];   // exp(alpha*f1)
__device__ float g_pp[NN];  // exp(f2)
__device__ float g_qq[NN];  // exp(alpha*f2)

__device__ __forceinline__ float to_tf32(float x) {
    asm("cvt.rna.tf32.f32 %0, %0;" : "+f"(x));
    return x;
}

__device__ __forceinline__ float elu_f(float x) {
    return x > 0.f ? x : expm1f(x);
}

// ---------------------------------------------------------------------------
// Kernel 1: Whext[:, 0:64] = tf32(h @ W); col 64 = 1.0 (denominator column);
//           cols 65..79 = 0 (pad).
// grid 128 blocks x 256 threads; each block: 64 rows, all 64 cols.
// ---------------------------------------------------------------------------
__global__ __launch_bounds__(256) void k_gemm_wh(
    const float* __restrict__ h, const float* __restrict__ W)
{
    __shared__ float hs[64][68];
    __shared__ float wt[64][68];   // wt[c][k] (transposed W tile)

    int t = threadIdx.x;
    int c = t & 63;        // output column
    int ry = t >> 6;       // 0..3
    int i0 = blockIdx.x * 64;

    float acc[16];
#pragma unroll
    for (int r = 0; r < 16; r++) acc[r] = 0.f;

    for (int kt = 0; kt < FIN; kt += 64) {
        __syncthreads();
#pragma unroll
        for (int it = 0; it < 16; it++) {
            int r = ry + 4 * it;
            hs[r][c] = h[(size_t)(i0 + r) * FIN + kt + c];
            wt[c][r] = W[(size_t)(kt + r) * FOUT + c];
        }
        __syncthreads();
#pragma unroll
        for (int k4 = 0; k4 < 16; k4++) {
            float4 wv = *(const float4*)&wt[c][k4 * 4];
#pragma unroll
            for (int r = 0; r < 16; r++) {
                float4 hh = *(const float4*)&hs[ry + 4 * r][k4 * 4];
                acc[r] += hh.x * wv.x + hh.y * wv.y + hh.z * wv.z + hh.w * wv.w;
            }
        }
    }
#pragma unroll
    for (int r = 0; r < 16; r++) {
        g_Whext[(size_t)(i0 + ry + 4 * r) * WH_STRIDE + c] = to_tf32(acc[r]);
    }
    if (c < 16) {
#pragma unroll
        for (int r = 0; r < 16; r++) {
            g_Whext[(size_t)(i0 + ry + 4 * r) * WH_STRIDE + 64 + c] =
                (c == 0) ? 1.0f : 0.0f;
        }
    }
}

// ---------------------------------------------------------------------------
// Kernel 2: per-node scalars: f1 = Wh·a1, f2 = Wh·a2, and the 4 exp factors.
// one warp per node.
// ---------------------------------------------------------------------------
__global__ __launch_bounds__(256) void k_fvec(const float* __restrict__ a)
{
    int warp = threadIdx.x >> 5;
    int lane = threadIdx.x & 31;
    int i = blockIdx.x * 8 + warp;

    const float* wh = &g_Whext[(size_t)i * WH_STRIDE];
    float w0 = wh[lane], w1 = wh[lane + 32];
    float s1 = w0 * a[lane] + w1 * a[lane + 32];
    float s2 = w0 * a[64 + lane] + w1 * a[96 + lane];
#pragma unroll
    for (int o = 16; o > 0; o >>= 1) {
        s1 += __shfl_xor_sync(0xffffffffu, s1, o);
        s2 += __shfl_xor_sync(0xffffffffu, s2, o);
    }
    if (lane == 0) {
        g_f1[i] = s1;
        g_f2[i] = s2;
        g_P[i] = expf(s1);
        g_Q[i] = expf(LRALPHA * s1);
        g_pp[i] = expf(s2);
        g_qq[i] = expf(LRALPHA * s2);
    }
}

// ---------------------------------------------------------------------------
// Kernel 3: fused masked-softmax attention + aggregation + elu.
// Block = 256 thr (8 warps) handles BM=64 rows; loops j over NN in BK=64 tiles.
// Per tile: build W tile (tf32) in SMEM from adj + exp factors, then
// mma.m16n8k8.tf32: acc[64x80] += Wtile[64x64] @ Whs[64x80].
// Col 64 of Whext is ones -> softmax denominator accumulates in col 64.
// Warp layout: mw = warp%4 (16 rows each), nw = warp/4 (40 cols each).
// ---------------------------------------------------------------------------
__global__ __launch_bounds__(256) void k_gat(
    const int* __restrict__ adj, float* __restrict__ out)
{
    __shared__ float Ws[BM][BK + 4];    // 64 x 68  (A tile, tf32-rounded)
    __shared__ float Whs[BK][BN + 8];   // 64 x 88  (B tile)
    __shared__ float Prs[BM], Qrs[BM], f1s[BM];
    __shared__ float dens[BM];

    int t = threadIdx.x;
    int i0 = blockIdx.x * BM;
    if (t < BM) {
        int i = i0 + t;
        Prs[t] = g_P[i];
        Qrs[t] = g_Q[i];
        f1s[t] = g_f1[i];
    }

    int warp = t >> 5, lane = t & 31;
    int mw = warp & 3;        // rows mw*16 .. +16
    int nw = warp >> 1 >> 1;  // == warp>>2 : 0/1 -> cols nw*40 .. +40
    int g = lane >> 2, tig = lane & 3;

    int jr = t >> 6;          // 0..3
    int jc = t & 63;          // 0..63

    float acc[5][4];
#pragma unroll
    for (int n = 0; n < 5; n++)
#pragma unroll
        for (int x = 0; x < 4; x++) acc[n][x] = 0.f;

    __syncthreads();          // row constants ready; Ws/Whs free

    for (int j0 = 0; j0 < NN; j0 += BK) {
        // per-tile column constants (tiny arrays, L1/L2-hot)
        float f2v = g_f2[j0 + jc];
        float pv  = g_pp[j0 + jc];
        float qv  = g_qq[j0 + jc];

        // 16 independent adjacency loads (streaming, coalesced 128B/warp)
        int av[16];
#pragma unroll
        for (int k = 0; k < 16; k++) {
            av[k] = __ldcs(&adj[(size_t)(i0 + jr + 4 * k) * NN + j0 + jc]);
        }

        // stage B tile: Whs[64][80] via float4 (already tf32-rounded)
        {
            const float4* src = (const float4*)&g_Whext[(size_t)j0 * WH_STRIDE];
#pragma unroll
            for (int it = 0; it < 5; it++) {
                int l = t + 256 * it;        // 0..1279
                int r = l / 20;
                int c4 = l % 20;
                float4 v = src[r * 20 + c4];
                *(float4*)&Whs[r][c4 * 4] = v;
            }
        }

        // build A tile: w = mask * (s>0 ? P_i*p_j : Q_i*q_j)
#pragma unroll
        for (int k = 0; k < 16; k++) {
            int r = jr + 4 * k;
            float s = f1s[r] + f2v;
            float w = (s > 0.f) ? (Prs[r] * pv) : (Qrs[r] * qv);
            w = (av[k] != 0) ? w : 0.f;
            Ws[r][jc] = to_tf32(w);
        }
        __syncthreads();

        // MMA: 8 k-steps x 5 n-tiles per warp
#pragma unroll
        for (int kt = 0; kt < 8; kt++) {
            int k = kt * 8;
            uint32_t A0 = __float_as_uint(Ws[mw * 16 + g][k + tig]);
            uint32_t A1 = __float_as_uint(Ws[mw * 16 + g + 8][k + tig]);
            uint32_t A2 = __float_as_uint(Ws[mw * 16 + g][k + tig + 4]);
            uint32_t A3 = __float_as_uint(Ws[mw * 16 + g + 8][k + tig + 4]);
#pragma unroll
            for (int nt = 0; nt < 5; nt++) {
                int n = nw * 40 + nt * 8;
                uint32_t B0 = __float_as_uint(Whs[k + tig][n + g]);
                uint32_t B1 = __float_as_uint(Whs[k + tig + 4][n + g]);
                asm volatile(
                    "mma.sync.aligned.m16n8k8.row.col.f32.tf32.tf32.f32 "
                    "{%0,%1,%2,%3}, {%4,%5,%6,%7}, {%8,%9}, {%0,%1,%2,%3};\n"
                    : "+f"(acc[nt][0]), "+f"(acc[nt][1]),
                      "+f"(acc[nt][2]), "+f"(acc[nt][3])
                    : "r"(A0), "r"(A1), "r"(A2), "r"(A3), "r"(B0), "r"(B1));
            }
        }
        __syncthreads();
    }

    // broadcast denominators (accumulated in logical column 64:
    // nw==1, nt==3, tig==0 -> regs c0 (row g), c2 (row g+8))
    if (nw == 1 && tig == 0) {
        dens[mw * 16 + g]     = acc[3][0];
        dens[mw * 16 + g + 8] = acc[3][2];
    }
    __syncthreads();

    // epilogue: out = elu(num / den)
#pragma unroll
    for (int nt = 0; nt < 5; nt++) {
        int nbase = nw * 40 + nt * 8 + 2 * tig;
        int r0 = mw * 16 + g, r1 = r0 + 8;
        float d0 = dens[r0], d1 = dens[r1];
        if (nbase < 64) {
            out[(size_t)(i0 + r0) * FOUT + nbase] = elu_f(acc[nt][0] / d0);
            out[(size_t)(i0 + r1) * FOUT + nbase] = elu_f(acc[nt][2] / d1);
        }
        if (nbase + 1 < 64) {
            out[(size_t)(i0 + r0) * FOUT + nbase + 1] = elu_f(acc[nt][1] / d0);
            out[(size_t)(i0 + r1) * FOUT + nbase + 1] = elu_f(acc[nt][3] / d1);
        }
    }
}

// ---------------------------------------------------------------------------
extern "C" void kernel_launch(void* const* d_in, const int* in_sizes, int n_in,
                              void* d_out, int out_size)
{
    const float* h   = (const float*)d_in[0];
    const int*   adj = (const int*)d_in[1];
    const float* W   = (const float*)d_in[2];
    const float* a   = (const float*)d_in[3];
    float* out = (float*)d_out;

    k_gemm_wh<<<NN / 64, 256>>>(h, W);
    k_fvec<<<NN / 8, 256>>>(a);
    k_gat<<<NN / BM, 256>>>(adj, out);
}

// round 2
// speedup vs baseline: 1.7248x; 1.7248x over previous
#include <cuda_runtime.h>
#include <math.h>
#include <stdint.h>

#define NN 8192
#define FIN 256
#define FOUT 64
#define LRALPHA 0.2f

#define BM 64
#define BK 64
#define BN 80          // 64 out cols + 1 ones(denominator) + 15 pad
#define WH_STRIDE 80
#define WHS_STRIDE 88  // padded SMEM stride for B tile
#define WS_STRIDE 68   // padded SMEM stride for A tile

// persistent scratch (no allocations allowed)
__device__ __align__(16) float g_Whext[NN * WH_STRIDE];  // ~2.6 MB
__device__ __align__(16) float4 g_rowc[NN];  // (f1, exp(f1), exp(a*f1), 0)
__device__ __align__(16) float4 g_colc[NN];  // (f2, exp(f2), exp(a*f2), 0)

__device__ __forceinline__ float to_tf32(float x) {
    asm("cvt.rna.tf32.f32 %0, %0;" : "+f"(x));
    return x;
}

__device__ __forceinline__ float elu_f(float x) {
    return x > 0.f ? x : expm1f(x);
}

__device__ __forceinline__ void cp_async16(uint32_t smem_addr, const void* gptr) {
    asm volatile("cp.async.cg.shared.global [%0], [%1], 16;\n"
                 :: "r"(smem_addr), "l"(gptr));
}
__device__ __forceinline__ void cp_commit() {
    asm volatile("cp.async.commit_group;\n" ::: "memory");
}
__device__ __forceinline__ void cp_wait1() {
    asm volatile("cp.async.wait_group 1;\n" ::: "memory");
}
__device__ __forceinline__ void cp_wait0() {
    asm volatile("cp.async.wait_group 0;\n" ::: "memory");
}

// ---------------------------------------------------------------------------
// Kernel 1: Whext[:, 0:64] = tf32(h @ W); col 64 = 1.0; cols 65..79 = 0.
// ---------------------------------------------------------------------------
__global__ __launch_bounds__(256) void k_gemm_wh(
    const float* __restrict__ h, const float* __restrict__ W)
{
    __shared__ float hs[64][68];
    __shared__ float wt[64][68];   // wt[c][k] (transposed W tile)

    int t = threadIdx.x;
    int c = t & 63;
    int ry = t >> 6;
    int i0 = blockIdx.x * 64;

    float acc[16];
#pragma unroll
    for (int r = 0; r < 16; r++) acc[r] = 0.f;

    for (int kt = 0; kt < FIN; kt += 64) {
        __syncthreads();
#pragma unroll
        for (int it = 0; it < 16; it++) {
            int r = ry + 4 * it;
            hs[r][c] = h[(size_t)(i0 + r) * FIN + kt + c];
            wt[c][r] = W[(size_t)(kt + r) * FOUT + c];
        }
        __syncthreads();
#pragma unroll
        for (int k4 = 0; k4 < 16; k4++) {
            float4 wv = *(const float4*)&wt[c][k4 * 4];
#pragma unroll
            for (int r = 0; r < 16; r++) {
                float4 hh = *(const float4*)&hs[ry + 4 * r][k4 * 4];
                acc[r] += hh.x * wv.x + hh.y * wv.y + hh.z * wv.z + hh.w * wv.w;
            }
        }
    }
#pragma unroll
    for (int r = 0; r < 16; r++) {
        g_Whext[(size_t)(i0 + ry + 4 * r) * WH_STRIDE + c] = to_tf32(acc[r]);
    }
    if (c < 16) {
#pragma unroll
        for (int r = 0; r < 16; r++) {
            g_Whext[(size_t)(i0 + ry + 4 * r) * WH_STRIDE + 64 + c] =
                (c == 0) ? 1.0f : 0.0f;
        }
    }
}

// ---------------------------------------------------------------------------
// Kernel 2: per-node scalars -> packed float4 row/col constants.
// ---------------------------------------------------------------------------
__global__ __launch_bounds__(256) void k_fvec(const float* __restrict__ a)
{
    int warp = threadIdx.x >> 5;
    int lane = threadIdx.x & 31;
    int i = blockIdx.x * 8 + warp;

    const float* wh = &g_Whext[(size_t)i * WH_STRIDE];
    float w0 = wh[lane], w1 = wh[lane + 32];
    float s1 = w0 * a[lane] + w1 * a[lane + 32];
    float s2 = w0 * a[64 + lane] + w1 * a[96 + lane];
#pragma unroll
    for (int o = 16; o > 0; o >>= 1) {
        s1 += __shfl_xor_sync(0xffffffffu, s1, o);
        s2 += __shfl_xor_sync(0xffffffffu, s2, o);
    }
    if (lane == 0) {
        g_rowc[i] = make_float4(s1, expf(s1), expf(LRALPHA * s1), 0.f);
        g_colc[i] = make_float4(s2, expf(s2), expf(LRALPHA * s2), 0.f);
    }
}

// ---------------------------------------------------------------------------
// Kernel 3: fused masked-softmax attention + aggregation + elu.
// 2-stage cp.async pipeline: adj(t+1) prefetched over tile t's compute,
// B tile cp.async'd with L2-hit latency hidden behind w-gen.
// Dynamic SMEM layout (bytes):
//   [0, 32768)        int  adjs[2][64][64]
//   [32768, 55296)    float Whs[64][88]
//   [55296, 72704)    float Ws[64][68]
//   [72704, 73728)    float4 rowc[64]
//   [73728, 73984)    float dens[64]
// ---------------------------------------------------------------------------
#define SMEM_TOTAL 73984

__global__ __launch_bounds__(256) void k_gat(
    const int* __restrict__ adj, float* __restrict__ out)
{
    extern __shared__ __align__(16) char smem[];
    int*    adjs = (int*)smem;                       // [2][64][64]
    float*  Whs  = (float*)(smem + 32768);           // [64][88]
    float*  Ws   = (float*)(smem + 55296);           // [64][68]
    float4* rowc = (float4*)(smem + 72704);          // [64]
    float*  dens = (float*)(smem + 73728);           // [64]

    uint32_t adjs_sa = (uint32_t)__cvta_generic_to_shared(adjs);
    uint32_t whs_sa  = (uint32_t)__cvta_generic_to_shared(Whs);

    int t = threadIdx.x;
    int i0 = blockIdx.x * BM;

    if (t < BM) rowc[t] = g_rowc[i0 + t];

    int warp = t >> 5, lane = t & 31;
    int mw = warp & 3;
    int nw = warp >> 2;
    int g = lane >> 2, tig = lane & 3;

    int jr = t >> 6;          // 0..3
    int jc = t & 63;          // 0..63

    float acc[5][4];
#pragma unroll
    for (int n = 0; n < 5; n++)
#pragma unroll
        for (int x = 0; x < 4; x++) acc[n][x] = 0.f;

    // ---- prologue: prefetch adj tile 0 into buffer 0
    {
#pragma unroll
        for (int it = 0; it < 4; it++) {
            int l = t + 256 * it;
            int r = l >> 4, c4 = l & 15;
            cp_async16(adjs_sa + (uint32_t)(r * 64 + c4 * 4) * 4,
                       &adj[(size_t)(i0 + r) * NN + c4 * 4]);
        }
        cp_commit();
    }

    for (int j0 = 0; j0 < NN; j0 += BK) {
        int buf = (j0 >> 6) & 1;

        // --- issue B(t) (L2-resident)
        {
            const char* src = (const char*)&g_Whext[(size_t)j0 * WH_STRIDE];
#pragma unroll
            for (int it = 0; it < 5; it++) {
                int l = t + 256 * it;          // 0..1279
                int r = l / 20, c4 = l % 20;
                cp_async16(whs_sa + (uint32_t)(r * WHS_STRIDE + c4 * 4) * 4,
                           src + ((size_t)r * WH_STRIDE + c4 * 4) * 4);
            }
        }
        cp_commit();

        // --- issue adj(t+1) (DRAM) into the other buffer
        if (j0 + BK < NN) {
            uint32_t dst = adjs_sa + (uint32_t)(buf ^ 1) * 16384;
#pragma unroll
            for (int it = 0; it < 4; it++) {
                int l = t + 256 * it;
                int r = l >> 4, c4 = l & 15;
                cp_async16(dst + (uint32_t)(r * 64 + c4 * 4) * 4,
                           &adj[(size_t)(i0 + r) * NN + (j0 + BK) + c4 * 4]);
            }
            cp_commit();
            cp_wait1();   // completes adj(t) + B(t), leaves adj(t+1) in flight
        } else {
            cp_wait0();
        }

        // col constants for this tile (small, cache-hot)
        float4 cc = g_colc[j0 + jc];

        __syncthreads();   // cp.async data visible to all

        // --- build A tile: w = mask * (s>0 ? P_i*p_j : Q_i*q_j)
        const int* at = &adjs[buf * 4096 + jr * 64 + jc];
#pragma unroll
        for (int k = 0; k < 16; k++) {
            int r = jr + 4 * k;
            float4 rc = rowc[r];
            int av = at[4 * k * 64];
            float s = rc.x + cc.x;
            float w = (s > 0.f) ? (rc.y * cc.y) : (rc.z * cc.z);
            w = av ? w : 0.f;
            Ws[r * WS_STRIDE + jc] = to_tf32(w);
        }
        __syncthreads();

        // --- MMA: 8 k-steps x 5 n-tiles per warp
#pragma unroll
        for (int kt = 0; kt < 8; kt++) {
            int k = kt * 8;
            uint32_t A0 = __float_as_uint(Ws[(mw * 16 + g) * WS_STRIDE + k + tig]);
            uint32_t A1 = __float_as_uint(Ws[(mw * 16 + g + 8) * WS_STRIDE + k + tig]);
            uint32_t A2 = __float_as_uint(Ws[(mw * 16 + g) * WS_STRIDE + k + tig + 4]);
            uint32_t A3 = __float_as_uint(Ws[(mw * 16 + g + 8) * WS_STRIDE + k + tig + 4]);
#pragma unroll
            for (int nt = 0; nt < 5; nt++) {
                int n = nw * 40 + nt * 8;
                uint32_t B0 = __float_as_uint(Whs[(k + tig) * WHS_STRIDE + n + g]);
                uint32_t B1 = __float_as_uint(Whs[(k + tig + 4) * WHS_STRIDE + n + g]);
                asm volatile(
                    "mma.sync.aligned.m16n8k8.row.col.f32.tf32.tf32.f32 "
                    "{%0,%1,%2,%3}, {%4,%5,%6,%7}, {%8,%9}, {%0,%1,%2,%3};\n"
                    : "+f"(acc[nt][0]), "+f"(acc[nt][1]),
                      "+f"(acc[nt][2]), "+f"(acc[nt][3])
                    : "r"(A0), "r"(A1), "r"(A2), "r"(A3), "r"(B0), "r"(B1));
            }
        }
        __syncthreads();
    }

    // denominators live in logical column 64: nw==1, nt==3, tig==0
    if (nw == 1 && tig == 0) {
        dens[mw * 16 + g]     = acc[3][0];
        dens[mw * 16 + g + 8] = acc[3][2];
    }
    __syncthreads();

    // epilogue: out = elu(num / den)
#pragma unroll
    for (int nt = 0; nt < 5; nt++) {
        int nbase = nw * 40 + nt * 8 + 2 * tig;
        int r0 = mw * 16 + g, r1 = r0 + 8;
        float d0 = dens[r0], d1 = dens[r1];
        if (nbase < 64) {
            out[(size_t)(i0 + r0) * FOUT + nbase] = elu_f(acc[nt][0] / d0);
            out[(size_t)(i0 + r1) * FOUT + nbase] = elu_f(acc[nt][2] / d1);
        }
        if (nbase + 1 < 64) {
            out[(size_t)(i0 + r0) * FOUT + nbase + 1] = elu_f(acc[nt][1] / d0);
            out[(size_t)(i0 + r1) * FOUT + nbase + 1] = elu_f(acc[nt][3] / d1);
        }
    }
}

// ---------------------------------------------------------------------------
extern "C" void kernel_launch(void* const* d_in, const int* in_sizes, int n_in,
                              void* d_out, int out_size)
{
    const float* h   = (const float*)d_in[0];
    const int*   adj = (const int*)d_in[1];
    const float* W   = (const float*)d_in[2];
    const float* a   = (const float*)d_in[3];
    float* out = (float*)d_out;

    cudaFuncSetAttribute(k_gat, cudaFuncAttributeMaxDynamicSharedMemorySize,
                         SMEM_TOTAL);

    k_gemm_wh<<<NN / 64, 256>>>(h, W);
    k_fvec<<<NN / 8, 256>>>(a);
    k_gat<<<NN / BM, 256, SMEM_TOTAL>>>(adj, out);
}

// round 3
// speedup vs baseline: 2.7252x; 1.5801x over previous
#include <cuda_runtime.h>
#include <math.h>
#include <stdint.h>

#define NN 8192
#define FIN 256
#define FOUT 64
#define LRALPHA 0.2f

#define BM 64
#define BK 64
#define WH_STRIDE 80
#define WHS_STRIDE 88  // padded SMEM stride for B tile
#define WS_STRIDE 68   // padded SMEM stride for A tile

#define NSPLIT 4
#define JCHUNK (NN / NSPLIT)   // 2048
#define PART_STRIDE 72

// persistent scratch (no allocations allowed)
__device__ __align__(16) float g_Whext[NN * WH_STRIDE];            // ~2.6 MB
__device__ __align__(16) float4 g_rowc[NN];  // (f1, exp(f1), exp(a*f1), 0)
__device__ __align__(16) float4 g_colc[NN];  // (f2, exp(f2), exp(a*f2), 0)
__device__ __align__(16) float g_part[(size_t)NSPLIT * NN * PART_STRIDE];

__device__ __forceinline__ float to_tf32(float x) {
    asm("cvt.rna.tf32.f32 %0, %0;" : "+f"(x));
    return x;
}

__device__ __forceinline__ float elu_f(float x) {
    return x > 0.f ? x : expm1f(x);
}

__device__ __forceinline__ void cp_async16(uint32_t smem_addr, const void* gptr) {
    asm volatile("cp.async.cg.shared.global [%0], [%1], 16;\n"
                 :: "r"(smem_addr), "l"(gptr));
}
__device__ __forceinline__ void cp_commit() {
    asm volatile("cp.async.commit_group;\n" ::: "memory");
}
__device__ __forceinline__ void cp_wait1() {
    asm volatile("cp.async.wait_group 1;\n" ::: "memory");
}
__device__ __forceinline__ void cp_wait0() {
    asm volatile("cp.async.wait_group 0;\n" ::: "memory");
}

// ---------------------------------------------------------------------------
// Kernel 1: Whext[:, 0:64] = tf32(h @ W); col 64 = 1.0; cols 65..79 = 0.
// 512 blocks x 256 thr; each block 16 rows.
// ---------------------------------------------------------------------------
__global__ __launch_bounds__(256) void k_gemm_wh(
    const float* __restrict__ h, const float* __restrict__ W)
{
    __shared__ float hs[16][68];
    __shared__ float wt[64][68];   // wt[c][k] (transposed W tile)

    int t = threadIdx.x;
    int c = t & 63;
    int ry = t >> 6;               // 0..3
    int i0 = blockIdx.x * 16;

    float acc[4];
#pragma unroll
    for (int r = 0; r < 4; r++) acc[r] = 0.f;

    for (int kt = 0; kt < FIN; kt += 64) {
        __syncthreads();
#pragma unroll
        for (int it = 0; it < 4; it++) {
            int r = ry + 4 * it;
            hs[r][c] = h[(size_t)(i0 + r) * FIN + kt + c];
        }
#pragma unroll
        for (int it = 0; it < 16; it++) {
            int r = ry + 4 * it;
            wt[c][r] = W[(size_t)(kt + r) * FOUT + c];
        }
        __syncthreads();
#pragma unroll
        for (int k4 = 0; k4 < 16; k4++) {
            float4 wv = *(const float4*)&wt[c][k4 * 4];
#pragma unroll
            for (int r = 0; r < 4; r++) {
                float4 hh = *(const float4*)&hs[ry + 4 * r][k4 * 4];
                acc[r] += hh.x * wv.x + hh.y * wv.y + hh.z * wv.z + hh.w * wv.w;
            }
        }
    }
#pragma unroll
    for (int r = 0; r < 4; r++) {
        g_Whext[(size_t)(i0 + ry + 4 * r) * WH_STRIDE + c] = to_tf32(acc[r]);
    }
    if (c < 16) {
#pragma unroll
        for (int r = 0; r < 4; r++) {
            g_Whext[(size_t)(i0 + ry + 4 * r) * WH_STRIDE + 64 + c] =
                (c == 0) ? 1.0f : 0.0f;
        }
    }
}

// ---------------------------------------------------------------------------
// Kernel 2: per-node scalars -> packed float4 row/col constants.
// ---------------------------------------------------------------------------
__global__ __launch_bounds__(256) void k_fvec(const float* __restrict__ a)
{
    int warp = threadIdx.x >> 5;
    int lane = threadIdx.x & 31;
    int i = blockIdx.x * 8 + warp;

    const float* wh = &g_Whext[(size_t)i * WH_STRIDE];
    float w0 = wh[lane], w1 = wh[lane + 32];
    float s1 = w0 * a[lane] + w1 * a[lane + 32];
    float s2 = w0 * a[64 + lane] + w1 * a[96 + lane];
#pragma unroll
    for (int o = 16; o > 0; o >>= 1) {
        s1 += __shfl_xor_sync(0xffffffffu, s1, o);
        s2 += __shfl_xor_sync(0xffffffffu, s2, o);
    }
    if (lane == 0) {
        g_rowc[i] = make_float4(s1, expf(s1), expf(LRALPHA * s1), 0.f);
        g_colc[i] = make_float4(s2, expf(s2), expf(LRALPHA * s2), 0.f);
    }
}

// ---------------------------------------------------------------------------
// Kernel 3: fused masked-softmax attention partial sums.
// grid = 512 CTAs: (i-tile 0..127) x (j-split 0..3). Each CTA covers
// BM=64 rows x JCHUNK=2048 j-cols, writes partial numerators (64 cols)
// + partial denominator (col 64) to g_part.
// 2 CTAs/SM co-resident to hide phase-barrier stalls.
// Dynamic SMEM layout (bytes):
//   [0, 32768)        int  adjs[2][64][64]
//   [32768, 55296)    float Whs[64][88]
//   [55296, 72704)    float Ws[64][68]
//   [72704, 73728)    float4 rowc[64]
// ---------------------------------------------------------------------------
#define SMEM_TOTAL 73728

__global__ __launch_bounds__(256, 2) void k_gat(
    const int* __restrict__ adj)
{
    extern __shared__ __align__(16) char smem[];
    int*    adjs = (int*)smem;                       // [2][64][64]
    float*  Whs  = (float*)(smem + 32768);           // [64][88]
    float*  Ws   = (float*)(smem + 55296);           // [64][68]
    float4* rowc = (float4*)(smem + 72704);          // [64]

    uint32_t adjs_sa = (uint32_t)__cvta_generic_to_shared(adjs);
    uint32_t whs_sa  = (uint32_t)__cvta_generic_to_shared(Whs);

    int t = threadIdx.x;
    int bx = blockIdx.x;
    int i0 = (bx >> 2) * BM;
    int split = bx & 3;
    int jstart = split * JCHUNK;
    int jend = jstart + JCHUNK;

    if (t < BM) rowc[t] = g_rowc[i0 + t];

    int warp = t >> 5, lane = t & 31;
    int mw = warp & 3;
    int nw = warp >> 2;
    int g = lane >> 2, tig = lane & 3;

    int jr = t >> 6;          // 0..3
    int jc = t & 63;          // 0..63

    float acc[5][4];
#pragma unroll
    for (int n = 0; n < 5; n++)
#pragma unroll
        for (int x = 0; x < 4; x++) acc[n][x] = 0.f;

    // ---- prologue: prefetch adj tile 0 into buffer 0
    {
#pragma unroll
        for (int it = 0; it < 4; it++) {
            int l = t + 256 * it;
            int r = l >> 4, c4 = l & 15;
            cp_async16(adjs_sa + (uint32_t)(r * 64 + c4 * 4) * 4,
                       &adj[(size_t)(i0 + r) * NN + jstart + c4 * 4]);
        }
        cp_commit();
    }

    for (int j0 = jstart; j0 < jend; j0 += BK) {
        int buf = (j0 >> 6) & 1;

        // --- issue B(t) (L2-resident)
        {
            const char* src = (const char*)&g_Whext[(size_t)j0 * WH_STRIDE];
#pragma unroll
            for (int it = 0; it < 5; it++) {
                int l = t + 256 * it;          // 0..1279
                int r = l / 20, c4 = l % 20;
                cp_async16(whs_sa + (uint32_t)(r * WHS_STRIDE + c4 * 4) * 4,
                           src + ((size_t)r * WH_STRIDE + c4 * 4) * 4);
            }
        }
        cp_commit();

        // --- issue adj(t+1) (DRAM) into the other buffer
        if (j0 + BK < jend) {
            uint32_t dst = adjs_sa + (uint32_t)(buf ^ 1) * 16384;
#pragma unroll
            for (int it = 0; it < 4; it++) {
                int l = t + 256 * it;
                int r = l >> 4, c4 = l & 15;
                cp_async16(dst + (uint32_t)(r * 64 + c4 * 4) * 4,
                           &adj[(size_t)(i0 + r) * NN + (j0 + BK) + c4 * 4]);
            }
            cp_commit();
            cp_wait1();   // completes adj(t) + B(t), leaves adj(t+1) in flight
        } else {
            cp_wait0();
        }

        // col constants for this tile (small, cache-hot)
        float4 cc = g_colc[j0 + jc];

        __syncthreads();   // cp.async data visible to all

        // --- build A tile: w = mask * (s>0 ? P_i*p_j : Q_i*q_j)
        const int* at = &adjs[buf * 4096 + jr * 64 + jc];
#pragma unroll
        for (int k = 0; k < 16; k++) {
            int r = jr + 4 * k;
            float4 rc = rowc[r];
            int av = at[4 * k * 64];
            float s = rc.x + cc.x;
            float w = (s > 0.f) ? (rc.y * cc.y) : (rc.z * cc.z);
            w = av ? w : 0.f;
            Ws[r * WS_STRIDE + jc] = to_tf32(w);
        }
        __syncthreads();

        // --- MMA: 8 k-steps x 5 n-tiles per warp
#pragma unroll
        for (int kt = 0; kt < 8; kt++) {
            int k = kt * 8;
            uint32_t A0 = __float_as_uint(Ws[(mw * 16 + g) * WS_STRIDE + k + tig]);
            uint32_t A1 = __float_as_uint(Ws[(mw * 16 + g + 8) * WS_STRIDE + k + tig]);
            uint32_t A2 = __float_as_uint(Ws[(mw * 16 + g) * WS_STRIDE + k + tig + 4]);
            uint32_t A3 = __float_as_uint(Ws[(mw * 16 + g + 8) * WS_STRIDE + k + tig + 4]);
#pragma unroll
            for (int nt = 0; nt < 5; nt++) {
                int n = nw * 40 + nt * 8;
                uint32_t B0 = __float_as_uint(Whs[(k + tig) * WHS_STRIDE + n + g]);
                uint32_t B1 = __float_as_uint(Whs[(k + tig + 4) * WHS_STRIDE + n + g]);
                asm volatile(
                    "mma.sync.aligned.m16n8k8.row.col.f32.tf32.tf32.f32 "
                    "{%0,%1,%2,%3}, {%4,%5,%6,%7}, {%8,%9}, {%0,%1,%2,%3};\n"
                    : "+f"(acc[nt][0]), "+f"(acc[nt][1]),
                      "+f"(acc[nt][2]), "+f"(acc[nt][3])
                    : "r"(A0), "r"(A1), "r"(A2), "r"(A3), "r"(B0), "r"(B1));
            }
        }
        __syncthreads();
    }

    // --- write partials: nums (cols 0..63) + den (col 64)
    float* pp = &g_part[((size_t)split * NN + i0) * PART_STRIDE];
    int r0 = mw * 16 + g, r1 = r0 + 8;
#pragma unroll
    for (int nt = 0; nt < 5; nt++) {
        int nbase = nw * 40 + nt * 8 + 2 * tig;
        if (nbase < 64) {
            pp[(size_t)r0 * PART_STRIDE + nbase] = acc[nt][0];
            pp[(size_t)r1 * PART_STRIDE + nbase] = acc[nt][2];
        }
        if (nbase + 1 < 64) {
            pp[(size_t)r0 * PART_STRIDE + nbase + 1] = acc[nt][1];
            pp[(size_t)r1 * PART_STRIDE + nbase + 1] = acc[nt][3];
        }
    }
    if (nw == 1 && tig == 0) {      // logical col 64 = denominator
        pp[(size_t)r0 * PART_STRIDE + 64] = acc[3][0];
        pp[(size_t)r1 * PART_STRIDE + 64] = acc[3][2];
    }
}

// ---------------------------------------------------------------------------
// Kernel 4: reduce partials across splits + elu.
// ---------------------------------------------------------------------------
__global__ __launch_bounds__(256) void k_reduce(float* __restrict__ out)
{
    int idx = blockIdx.x * 256 + threadIdx.x;   // 0 .. NN*64
    int i = idx >> 6;
    int c = idx & 63;

    float num = 0.f, den = 0.f;
#pragma unroll
    for (int s = 0; s < NSPLIT; s++) {
        const float* pp = &g_part[((size_t)s * NN + i) * PART_STRIDE];
        num += pp[c];
        den += pp[64];
    }
    out[(size_t)i * FOUT + c] = elu_f(num / den);
}

// ---------------------------------------------------------------------------
extern "C" void kernel_launch(void* const* d_in, const int* in_sizes, int n_in,
                              void* d_out, int out_size)
{
    const float* h   = (const float*)d_in[0];
    const int*   adj = (const int*)d_in[1];
    const float* W   = (const float*)d_in[2];
    const float* a   = (const float*)d_in[3];
    float* out = (float*)d_out;

    cudaFuncSetAttribute(k_gat, cudaFuncAttributeMaxDynamicSharedMemorySize,
                         SMEM_TOTAL);

    k_gemm_wh<<<NN / 16, 256>>>(h, W);
    k_fvec<<<NN / 8, 256>>>(a);
    k_gat<<<(NN / BM) * NSPLIT, 256, SMEM_TOTAL>>>(adj);
    k_reduce<<<NN * FOUT / 256, 256>>>(out);
}

// round 5
// speedup vs baseline: 4.5161x; 1.6572x over previous
#include <cuda_runtime.h>
#include <cuda_fp16.h>
#include <math.h>
#include <stdint.h>

#define NN 8192
#define FIN 256
#define FOUT 64
#define LRALPHA 0.2f

#define BM 128
#define BK 64
#define NB 80               // B n-rows: 64 out + ones(64) + zeros(65..79)
#define ASTR 72             // A SMEM stride (halves)
#define BSTR 72             // B SMEM stride (halves)
#define NSPLIT 4
#define JCHUNK (NN / NSPLIT)        // 2048
#define NTILES (JCHUNK / BK)        // 32
#define PART_STRIDE 72

// ---- persistent scratch (no allocations allowed) ----
__device__ __align__(16) __half g_Wht[(size_t)NB * NN];   // transposed fp16 Wh + ones/zeros
__device__ __align__(16) float4 g_rowc[NN];  // (f1, exp(f1-m), exp(.2f1-m), 0)
__device__ __align__(16) float4 g_colc[NN];  // (f2, exp(f2),   exp(.2f2),   0)
__device__ float g_f1[NN];
__device__ float g_f2[NN];
__device__ unsigned int g_m2key;
__device__ __align__(16) float g_part[(size_t)NSPLIT * NN * PART_STRIDE];

__device__ __forceinline__ float elu_f(float x) {
    return x > 0.f ? x : expm1f(x);
}
__device__ __forceinline__ unsigned int fkey(float x) {
    unsigned int b = __float_as_uint(x);
    return (b & 0x80000000u) ? ~b : (b | 0x80000000u);
}
__device__ __forceinline__ float fdecode(unsigned int k) {
    return __uint_as_float((k & 0x80000000u) ? (k & 0x7fffffffu) : ~k);
}
__device__ __forceinline__ void cp_async16(uint32_t smem_addr, const void* gptr) {
    asm volatile("cp.async.cg.shared.global [%0], [%1], 16;\n"
                 :: "r"(smem_addr), "l"(gptr));
}
__device__ __forceinline__ void cp_commit() {
    asm volatile("cp.async.commit_group;\n" ::: "memory");
}
__device__ __forceinline__ void cp_wait1() {
    asm volatile("cp.async.wait_group 1;\n" ::: "memory");
}
__device__ __forceinline__ void cp_wait0() {
    asm volatile("cp.async.wait_group 0;\n" ::: "memory");
}

// ---------------------------------------------------------------------------
// Kernel 1: g_Wht[c][i] = fp16((h @ W)[i][c]); row 64 = 1; rows 65..79 = 0.
// 512 blocks x 256 thr; each block 16 i-rows, all 64 cols.
// ---------------------------------------------------------------------------
__global__ __launch_bounds__(256) void k_gemm_wh(
    const float* __restrict__ h, const float* __restrict__ W)
{
    __shared__ float hs[16][68];
    __shared__ float wt[64][68];
    __shared__ float ts[64][17];   // transpose staging [c][r_local]

    int t = threadIdx.x;
    int c = t & 63;
    int ry = t >> 6;               // 0..3
    int i0 = blockIdx.x * 16;

    if (blockIdx.x == 0 && t == 0) g_m2key = 0u;  // reset max key each replay

    float acc[4];
#pragma unroll
    for (int r = 0; r < 4; r++) acc[r] = 0.f;

    for (int kt = 0; kt < FIN; kt += 64) {
        __syncthreads();
#pragma unroll
        for (int it = 0; it < 4; it++) {
            int r = ry + 4 * it;
            hs[r][c] = h[(size_t)(i0 + r) * FIN + kt + c];
        }
#pragma unroll
        for (int it = 0; it < 16; it++) {
            int r = ry + 4 * it;
            wt[c][r] = W[(size_t)(kt + r) * FOUT + c];
        }
        __syncthreads();
#pragma unroll
        for (int k4 = 0; k4 < 16; k4++) {
            float4 wv = *(const float4*)&wt[c][k4 * 4];
#pragma unroll
            for (int r = 0; r < 4; r++) {
                float4 hh = *(const float4*)&hs[ry + 4 * r][k4 * 4];
                acc[r] += hh.x * wv.x + hh.y * wv.y + hh.z * wv.z + hh.w * wv.w;
            }
        }
    }
#pragma unroll
    for (int r = 0; r < 4; r++) ts[c][ry + 4 * r] = acc[r];
    __syncthreads();

    // transposed fp16 write: thread t -> row c2 = t>>2, i-chunk q = t&3 (4 halves)
    {
        int c2 = t >> 2, q = t & 3;
        __half2 h0 = __floats2half2_rn(ts[c2][q * 4 + 0], ts[c2][q * 4 + 1]);
        __half2 h1 = __floats2half2_rn(ts[c2][q * 4 + 2], ts[c2][q * 4 + 3]);
        __half2* dst = (__half2*)&g_Wht[(size_t)c2 * NN + i0 + q * 4];
        dst[0] = h0;
        dst[1] = h1;
    }
    // ones / zero rows 64..79 for this i-slice
    {
        int rr = 64 + (t >> 4), ii = t & 15;
        g_Wht[(size_t)rr * NN + i0 + ii] = (rr == 64) ? __float2half(1.0f)
                                                      : __float2half(0.0f);
    }
}

// ---------------------------------------------------------------------------
// Kernel 2: f1/f2 per node + global max of f2 (order-preserving uint atomicMax).
// ---------------------------------------------------------------------------
__global__ __launch_bounds__(256) void k_fvec(const float* __restrict__ a)
{
    int i = blockIdx.x * 256 + threadIdx.x;
    float s1 = 0.f, s2 = 0.f;
#pragma unroll 8
    for (int c = 0; c < 64; c++) {
        float v = __half2float(g_Wht[(size_t)c * NN + i]);
        s1 += v * __ldg(&a[c]);
        s2 += v * __ldg(&a[64 + c]);
    }
    g_f1[i] = s1;
    g_f2[i] = s2;
    float m = s2;
#pragma unroll
    for (int o = 16; o > 0; o >>= 1)
        m = fmaxf(m, __shfl_xor_sync(0xffffffffu, m, o));
    if ((threadIdx.x & 31) == 0) atomicMax(&g_m2key, fkey(m));
}

// ---------------------------------------------------------------------------
// Kernel 3: row/col exp constants with per-row rescale m_i = lrelu(f1_i + M2).
// All scaled weights <= 1 -> fp16-safe; num/den invariant to row scale.
// ---------------------------------------------------------------------------
__global__ __launch_bounds__(256) void k_consts()
{
    int i = blockIdx.x * 256 + threadIdx.x;
    float M2 = fdecode(g_m2key);
    float f1 = g_f1[i], f2 = g_f2[i];
    float z = f1 + M2;
    float m = (z > 0.f) ? z : LRALPHA * z;
    g_rowc[i] = make_float4(f1, expf(f1 - m), expf(LRALPHA * f1 - m), 0.f);
    g_colc[i] = make_float4(f2, expf(f2), expf(LRALPHA * f2), 0.f);
}

// ---------------------------------------------------------------------------
// Kernel 4: fused masked-softmax attention partial sums (fp16 m16n8k16 MMA).
// grid = 64 i-blocks x 4 j-splits = 256 CTAs (1 wave at 2 CTAs/SM), 256 thr.
// Per j-tile: cp.async adj(XOR-swizzled chunks)/B/colc (double-buffered, one
// commit group per tile); w-gen builds fp16 A[128x64] (<=1 after rescale);
// 8 warps do 320 m16n8k16 MMAs (acc fp32, 2 m-tiles x 5 n-tiles per warp).
// Logical col 64 of B is ones -> denominator accumulates in acc col 64.
// SMEM (bytes):
//   [0,      65536)  int  adjs[2][128][64]   (chunk-swizzled)
//   [65536,  83968)  half A[128][72]
//   [83968, 107008)  half B[2][80][72]
//   [107008,109056)  float4 colcs[2][64]
// ---------------------------------------------------------------------------
#define SM_ADJ   0
#define SM_A     65536
#define SM_B     83968
#define SM_COLC  107008
#define SMEM_TOTAL 109056

__global__ __launch_bounds__(256, 2) void k_gat(const int* __restrict__ adj)
{
    extern __shared__ __align__(16) char smem[];
    uint32_t sbase = (uint32_t)__cvta_generic_to_shared(smem);

    int t = threadIdx.x;
    int warp = t >> 5, lane = t & 31;
    int i0 = (blockIdx.x >> 2) * BM;
    int split = blockIdx.x & 3;
    int jstart = split * JCHUNK;

    // w-gen mapping: row wr, column half ch (32 cols each)
    int wr = warp * 16 + (lane & 15);
    int ch = lane >> 4;
    int c0 = ch * 32;
    float4 rc = g_rowc[i0 + wr];

    // MMA mapping
    int mb = (warp & 3) * 32;      // 32 rows (2 m-tiles)
    int nb = (warp >> 2) * 40;     // 40 cols (5 n-tiles)
    int g = lane >> 2, tig = lane & 3;

    float acc[2][5][4];
#pragma unroll
    for (int m = 0; m < 2; m++)
#pragma unroll
        for (int n = 0; n < 5; n++)
#pragma unroll
            for (int x = 0; x < 4; x++) acc[m][n][x] = 0.f;

    const uint32_t* As32 = (const uint32_t*)(smem + SM_A);

    // ---- prologue: adj0 + B0 + colc0 into buffer 0
    {
#pragma unroll
        for (int it = 0; it < 8; it++) {
            int l = t + 256 * it;                 // 0..2047
            int rr = l >> 4, c4 = l & 15;
            int p = c4 ^ (rr & 15);
            cp_async16(sbase + SM_ADJ + (uint32_t)(rr * 256 + p * 16),
                       &adj[(size_t)(i0 + rr) * NN + jstart + c4 * 4]);
        }
#pragma unroll
        for (int it = 0; it < 3; it++) {
            int l = t + 256 * it;                 // 0..639
            if (l < 640) {
                int n = l >> 3, kc = l & 7;
                cp_async16(sbase + SM_B + (uint32_t)(n * (BSTR * 2) + kc * 16),
                           &g_Wht[(size_t)n * NN + jstart + kc * 8]);
            }
        }
        if (t < 64)
            cp_async16(sbase + SM_COLC + (uint32_t)t * 16, &g_colc[jstart + t]);
        cp_commit();
    }

    for (int tt = 0; tt < NTILES; tt++) {
        int buf = tt & 1;
        int j0 = jstart + tt * BK;

        // 1. all warps done with prev MMA (B[buf^1]) and prev w-gen (adj[buf^1])
        __syncthreads();

        // 2. issue tile tt+1 into buf^1
        if (tt + 1 < NTILES) {
            int jn = j0 + BK;
            uint32_t ad = sbase + SM_ADJ + (uint32_t)(buf ^ 1) * 32768;
            uint32_t bd = sbase + SM_B + (uint32_t)(buf ^ 1) * (NB * BSTR * 2);
            uint32_t cd = sbase + SM_COLC + (uint32_t)(buf ^ 1) * 1024;
#pragma unroll
            for (int it = 0; it < 8; it++) {
                int l = t + 256 * it;
                int rr = l >> 4, c4 = l & 15;
                int p = c4 ^ (rr & 15);
                cp_async16(ad + (uint32_t)(rr * 256 + p * 16),
                           &adj[(size_t)(i0 + rr) * NN + jn + c4 * 4]);
            }
#pragma unroll
            for (int it = 0; it < 3; it++) {
                int l = t + 256 * it;
                if (l < 640) {
                    int n = l >> 3, kc = l & 7;
                    cp_async16(bd + (uint32_t)(n * (BSTR * 2) + kc * 16),
                               &g_Wht[(size_t)n * NN + jn + kc * 8]);
                }
            }
            if (t < 64) cp_async16(cd + (uint32_t)t * 16, &g_colc[jn + t]);
            cp_commit();
            cp_wait1();   // tile tt data complete; tt+1 in flight
        } else {
            cp_wait0();
        }

        // 3. visibility of tile tt
        __syncthreads();

        // 4. w-gen -> fp16 A[128][64]
        {
            const char* ab = smem + SM_ADJ + buf * 32768 + wr * 256;
            __half2* arow = (__half2*)(smem + SM_A + (wr * ASTR + c0) * 2);
            const float4* cl = (const float4*)(smem + SM_COLC + buf * 1024);
#pragma unroll
            for (int q = 0; q < 8; q++) {
                int lc = 8 * ch + q;
                int p = lc ^ (wr & 15);
                int4 av = *(const int4*)(ab + p * 16);
                float4 x0 = cl[c0 + 4 * q + 0];
                float4 x1 = cl[c0 + 4 * q + 1];
                float4 x2 = cl[c0 + 4 * q + 2];
                float4 x3 = cl[c0 + 4 * q + 3];
                float w0 = ((rc.x + x0.x) > 0.f) ? rc.y * x0.y : rc.z * x0.z;
                float w1 = ((rc.x + x1.x) > 0.f) ? rc.y * x1.y : rc.z * x1.z;
                float w2 = ((rc.x + x2.x) > 0.f) ? rc.y * x2.y : rc.z * x2.z;
                float w3 = ((rc.x + x3.x) > 0.f) ? rc.y * x3.y : rc.z * x3.z;
                w0 = av.x ? w0 : 0.f;
                w1 = av.y ? w1 : 0.f;
                w2 = av.z ? w2 : 0.f;
                w3 = av.w ? w3 : 0.f;
                arow[2 * q + 0] = __floats2half2_rn(w0, w1);
                arow[2 * q + 1] = __floats2half2_rn(w2, w3);
            }
        }
        __syncthreads();

        // 5. MMA: 4 k-steps x (2 m-tiles x 5 n-tiles)
        const uint32_t* Bs32 = (const uint32_t*)(smem + SM_B + buf * (NB * BSTR * 2));
#pragma unroll
        for (int kt = 0; kt < 4; kt++) {
            int kb = kt * 16 + 2 * tig;          // half index (even)
            uint32_t a0[4], a1[4];
            {
                int r0 = mb + g;
                a0[0] = As32[r0 * (ASTR / 2) + (kb >> 1)];
                a0[1] = As32[(r0 + 8) * (ASTR / 2) + (kb >> 1)];
                a0[2] = As32[r0 * (ASTR / 2) + ((kb + 8) >> 1)];
                a0[3] = As32[(r0 + 8) * (ASTR / 2) + ((kb + 8) >> 1)];
                int r1 = mb + 16 + g;
                a1[0] = As32[r1 * (ASTR / 2) + (kb >> 1)];
                a1[1] = As32[(r1 + 8) * (ASTR / 2) + (kb >> 1)];
                a1[2] = As32[r1 * (ASTR / 2) + ((kb + 8) >> 1)];
                a1[3] = As32[(r1 + 8) * (ASTR / 2) + ((kb + 8) >> 1)];
            }
#pragma unroll
            for (int nt = 0; nt < 5; nt++) {
                int n = nb + nt * 8 + g;
                uint32_t b0 = Bs32[n * (BSTR / 2) + (kb >> 1)];
                uint32_t b1 = Bs32[n * (BSTR / 2) + ((kb + 8) >> 1)];
                asm volatile(
                    "mma.sync.aligned.m16n8k16.row.col.f32.f16.f16.f32 "
                    "{%0,%1,%2,%3}, {%4,%5,%6,%7}, {%8,%9}, {%0,%1,%2,%3};\n"
                    : "+f"(acc[0][nt][0]), "+f"(acc[0][nt][1]),
                      "+f"(acc[0][nt][2]), "+f"(acc[0][nt][3])
                    : "r"(a0[0]), "r"(a0[1]), "r"(a0[2]), "r"(a0[3]),
                      "r"(b0), "r"(b1));
                asm volatile(
                    "mma.sync.aligned.m16n8k16.row.col.f32.f16.f16.f32 "
                    "{%0,%1,%2,%3}, {%4,%5,%6,%7}, {%8,%9}, {%0,%1,%2,%3};\n"
                    : "+f"(acc[1][nt][0]), "+f"(acc[1][nt][1]),
                      "+f"(acc[1][nt][2]), "+f"(acc[1][nt][3])
                    : "r"(a1[0]), "r"(a1[1]), "r"(a1[2]), "r"(a1[3]),
                      "r"(b0), "r"(b1));
            }
        }
    }

    // ---- write partials: nums (cols 0..63) + den (logical col 64)
    float* pp = &g_part[((size_t)split * NN + i0) * PART_STRIDE];
#pragma unroll
    for (int m = 0; m < 2; m++) {
        int r0 = mb + m * 16 + g, r1 = r0 + 8;
#pragma unroll
        for (int nt = 0; nt < 5; nt++) {
            int nb2 = nb + nt * 8 + 2 * tig;
            if (nb2 < 64) {
                pp[(size_t)r0 * PART_STRIDE + nb2] = acc[m][nt][0];
                pp[(size_t)r1 * PART_STRIDE + nb2] = acc[m][nt][2];
            }
            if (nb2 + 1 < 64) {
                pp[(size_t)r0 * PART_STRIDE + nb2 + 1] = acc[m][nt][1];
                pp[(size_t)r1 * PART_STRIDE + nb2 + 1] = acc[m][nt][3];
            }
        }
        if (nb == 40 && tig == 0) {    // col 64 = 40 + 3*8 + 0
            pp[(size_t)r0 * PART_STRIDE + 64] = acc[m][3][0];
            pp[(size_t)r1 * PART_STRIDE + 64] = acc[m][3][2];
        }
    }
}

// ---------------------------------------------------------------------------
// Kernel 5: reduce partials across splits + elu.
// ---------------------------------------------------------------------------
__global__ __launch_bounds__(256) void k_reduce(float* __restrict__ out)
{
    int idx = blockIdx.x * 256 + threadIdx.x;   // 0 .. NN*64
    int i = idx >> 6;
    int c = idx & 63;

    float num = 0.f, den = 0.f;
#pragma unroll
    for (int s = 0; s < NSPLIT; s++) {
        const float* pp = &g_part[((size_t)s * NN + i) * PART_STRIDE];
        num += pp[c];
        den += pp[64];
    }
    out[(size_t)i * FOUT + c] = elu_f(num / den);
}

// ---------------------------------------------------------------------------
extern "C" void kernel_launch(void* const* d_in, const int* in_sizes, int n_in,
                              void* d_out, int out_size)
{
    const float* h   = (const float*)d_in[0];
    const int*   adj = (const int*)d_in[1];
    const float* W   = (const float*)d_in[2];
    const float* a   = (const float*)d_in[3];
    float* out = (float*)d_out;

    cudaFuncSetAttribute(k_gat, cudaFuncAttributeMaxDynamicSharedMemorySize,
                         SMEM_TOTAL);

    k_gemm_wh<<<NN / 16, 256>>>(h, W);
    k_fvec<<<NN / 256, 256>>>(a);
    k_consts<<<NN / 256, 256>>>();
    k_gat<<<(NN / BM) * NSPLIT, 256, SMEM_TOTAL>>>(adj);
    k_reduce<<<NN * FOUT / 256, 256>>>(out);
}

// round 6
// speedup vs baseline: 5.0185x; 1.1112x over previous
#include <cuda_runtime.h>
#include <cuda_fp16.h>
#include <math.h>
#include <stdint.h>

#define NN 8192
#define FIN 256
#define FOUT 64
#define LRALPHA 0.2f

#define BM 128
#define BK 64
#define NB 80               // B n-rows: 64 out + ones(64) + zeros(65..79)
#define ASTR 72             // A SMEM stride (halves)
#define BSTR 72             // B SMEM stride (halves)
#define NSPLIT 4
#define JCHUNK (NN / NSPLIT)        // 2048
#define NTILES (JCHUNK / BK)        // 32
#define PART_STRIDE 72

// ---- persistent scratch (no allocations allowed) ----
__device__ __align__(16) __half g_Wht[(size_t)NB * NN];   // transposed fp16 Wh + ones/zeros
__device__ __align__(16) float4 g_rowc[NN];  // (f1, exp(f1-m), exp(.2f1-m), 0)
__device__ __align__(16) float4 g_colc[NN];  // (f2, exp(f2),   exp(.2f2),   0)
__device__ float g_f1[NN];
__device__ float g_f2[NN];
__device__ unsigned int g_m2key;
__device__ __align__(16) float g_part[(size_t)NSPLIT * NN * PART_STRIDE];

__device__ __forceinline__ float elu_f(float x) {
    return x > 0.f ? x : expm1f(x);
}
__device__ __forceinline__ unsigned int fkey(float x) {
    unsigned int b = __float_as_uint(x);
    return (b & 0x80000000u) ? ~b : (b | 0x80000000u);
}
__device__ __forceinline__ float fdecode(unsigned int k) {
    return __uint_as_float((k & 0x80000000u) ? (k & 0x7fffffffu) : ~k);
}
__device__ __forceinline__ void cp_async16(uint32_t smem_addr, const void* gptr) {
    asm volatile("cp.async.cg.shared.global [%0], [%1], 16;\n"
                 :: "r"(smem_addr), "l"(gptr));
}
__device__ __forceinline__ void cp_commit() {
    asm volatile("cp.async.commit_group;\n" ::: "memory");
}
__device__ __forceinline__ void cp_wait1() {
    asm volatile("cp.async.wait_group 1;\n" ::: "memory");
}
__device__ __forceinline__ void cp_wait0() {
    asm volatile("cp.async.wait_group 0;\n" ::: "memory");
}

// ---------------------------------------------------------------------------
// Kernel 1: g_Wht[c][i] = fp16((h @ W)[i][c]); row 64 = 1; rows 65..79 = 0.
// ---------------------------------------------------------------------------
__global__ __launch_bounds__(256) void k_gemm_wh(
    const float* __restrict__ h, const float* __restrict__ W)
{
    __shared__ float hs[16][68];
    __shared__ float wt[64][68];
    __shared__ float ts[64][17];   // transpose staging [c][r_local]

    int t = threadIdx.x;
    int c = t & 63;
    int ry = t >> 6;               // 0..3
    int i0 = blockIdx.x * 16;

    if (blockIdx.x == 0 && t == 0) g_m2key = 0u;  // reset max key each replay

    float acc[4];
#pragma unroll
    for (int r = 0; r < 4; r++) acc[r] = 0.f;

    for (int kt = 0; kt < FIN; kt += 64) {
        __syncthreads();
#pragma unroll
        for (int it = 0; it < 4; it++) {
            int r = ry + 4 * it;
            hs[r][c] = h[(size_t)(i0 + r) * FIN + kt + c];
        }
#pragma unroll
        for (int it = 0; it < 16; it++) {
            int r = ry + 4 * it;
            wt[c][r] = W[(size_t)(kt + r) * FOUT + c];
        }
        __syncthreads();
#pragma unroll
        for (int k4 = 0; k4 < 16; k4++) {
            float4 wv = *(const float4*)&wt[c][k4 * 4];
#pragma unroll
            for (int r = 0; r < 4; r++) {
                float4 hh = *(const float4*)&hs[ry + 4 * r][k4 * 4];
                acc[r] += hh.x * wv.x + hh.y * wv.y + hh.z * wv.z + hh.w * wv.w;
            }
        }
    }
#pragma unroll
    for (int r = 0; r < 4; r++) ts[c][ry + 4 * r] = acc[r];
    __syncthreads();

    // transposed fp16 write
    {
        int c2 = t >> 2, q = t & 3;
        __half2 h0 = __floats2half2_rn(ts[c2][q * 4 + 0], ts[c2][q * 4 + 1]);
        __half2 h1 = __floats2half2_rn(ts[c2][q * 4 + 2], ts[c2][q * 4 + 3]);
        __half2* dst = (__half2*)&g_Wht[(size_t)c2 * NN + i0 + q * 4];
        dst[0] = h0;
        dst[1] = h1;
    }
    // ones / zero rows 64..79 for this i-slice
    {
        int rr = 64 + (t >> 4), ii = t & 15;
        g_Wht[(size_t)rr * NN + i0 + ii] = (rr == 64) ? __float2half(1.0f)
                                                      : __float2half(0.0f);
    }
}

// ---------------------------------------------------------------------------
// Kernel 2: f1/f2 per node + global max of f2.
// ---------------------------------------------------------------------------
__global__ __launch_bounds__(256) void k_fvec(const float* __restrict__ a)
{
    int i = blockIdx.x * 256 + threadIdx.x;
    float s1 = 0.f, s2 = 0.f;
#pragma unroll 8
    for (int c = 0; c < 64; c++) {
        float v = __half2float(g_Wht[(size_t)c * NN + i]);
        s1 += v * __ldg(&a[c]);
        s2 += v * __ldg(&a[64 + c]);
    }
    g_f1[i] = s1;
    g_f2[i] = s2;
    float m = s2;
#pragma unroll
    for (int o = 16; o > 0; o >>= 1)
        m = fmaxf(m, __shfl_xor_sync(0xffffffffu, m, o));
    if ((threadIdx.x & 31) == 0) atomicMax(&g_m2key, fkey(m));
}

// ---------------------------------------------------------------------------
// Kernel 3: row/col exp constants, per-row rescale m_i = lrelu(f1_i + M2).
// ---------------------------------------------------------------------------
__global__ __launch_bounds__(256) void k_consts()
{
    int i = blockIdx.x * 256 + threadIdx.x;
    float M2 = fdecode(g_m2key);
    float f1 = g_f1[i], f2 = g_f2[i];
    float z = f1 + M2;
    float m = (z > 0.f) ? z : LRALPHA * z;
    g_rowc[i] = make_float4(f1, expf(f1 - m), expf(LRALPHA * f1 - m), 0.f);
    g_colc[i] = make_float4(f2, expf(f2), expf(LRALPHA * f2), 0.f);
}

// ---------------------------------------------------------------------------
// Kernel 4: fused masked-softmax attention partials (fp16 m16n8k16 MMA).
// grid = 64 i-blocks x 4 j-splits = 256 CTAs, 256 thr, 2 CTAs/SM.
// Adjacency: direct LDG.64 (__ldcs) -> registers, 16 independent loads per
// thread per tile (warp w owns rows 16w..16w+15, lane l owns cols 2l,2l+1:
// one 256B coalesced transaction per row). Loads for tile t+1 issue right
// after tile t is consumed and fly over the whole MMA phase.
// B/colc: cp.async double-buffer (L2-hot). A single-buffered between syncs.
// SMEM (bytes):
//   [0,     18432)  half  A[128][72]
//   [18432, 41472)  half  B[2][80][72]
//   [41472, 43520)  float4 colcs[2][64]
//   [43520, 45568)  float4 rowcs[128]
// ---------------------------------------------------------------------------
#define SM_A     0
#define SM_B     18432
#define SM_COLC  41472
#define SM_ROWC  43520
#define SMEM_TOTAL 45568

__global__ __launch_bounds__(256, 2) void k_gat(const int* __restrict__ adj)
{
    extern __shared__ __align__(16) char smem[];
    uint32_t sbase = (uint32_t)__cvta_generic_to_shared(smem);

    int t = threadIdx.x;
    int warp = t >> 5, lane = t & 31;
    int i0 = (blockIdx.x >> 2) * BM;
    int split = blockIdx.x & 3;
    int jstart = split * JCHUNK;

    // fixed row constants for the whole CTA
    if (t < 128) ((float4*)(smem + SM_ROWC))[t] = g_rowc[i0 + t];

    // w-gen mapping: warp -> rows 16w..16w+15; lane -> cols 2l, 2l+1
    int wrow0 = warp * 16;
    const int* aptr = adj + (size_t)(i0 + wrow0) * NN + 2 * lane;

    // MMA mapping
    int mb = (warp & 3) * 32;      // 32 rows (2 m-tiles)
    int nb = (warp >> 2) * 40;     // 40 cols (5 n-tiles)
    int g = lane >> 2, tig = lane & 3;

    float acc[2][5][4];
#pragma unroll
    for (int m = 0; m < 2; m++)
#pragma unroll
        for (int n = 0; n < 5; n++)
#pragma unroll
            for (int x = 0; x < 4; x++) acc[m][n][x] = 0.f;

    const uint32_t* As32 = (const uint32_t*)(smem + SM_A);

    // ---- prologue: B(0)+colc(0) cp.async into buf 0; adj(0) -> registers
    {
#pragma unroll
        for (int it = 0; it < 3; it++) {
            int l = t + 256 * it;
            if (l < 640) {
                int n = l >> 3, kc = l & 7;
                cp_async16(sbase + SM_B + (uint32_t)(n * (BSTR * 2) + kc * 16),
                           &g_Wht[(size_t)n * NN + jstart + kc * 8]);
            }
        }
        if (t < 64)
            cp_async16(sbase + SM_COLC + (uint32_t)t * 16, &g_colc[jstart + t]);
        cp_commit();
    }

    int2 av[16];
#pragma unroll
    for (int r = 0; r < 16; r++)
        av[r] = __ldcs((const int2*)(aptr + (size_t)r * NN + jstart));

    for (int tt = 0; tt < NTILES; tt++) {
        int buf = tt & 1;
        int j0 = jstart + tt * BK;

        // 1. all warps done with MMA(tt-1) (reads B[buf^1]) before refill
        __syncthreads();

        // 2. issue B(tt+1)/colc(tt+1) into buf^1
        if (tt + 1 < NTILES) {
            int jn = j0 + BK;
            uint32_t bd = sbase + SM_B + (uint32_t)(buf ^ 1) * (NB * BSTR * 2);
            uint32_t cd = sbase + SM_COLC + (uint32_t)(buf ^ 1) * 1024;
#pragma unroll
            for (int it = 0; it < 3; it++) {
                int l = t + 256 * it;
                if (l < 640) {
                    int n = l >> 3, kc = l & 7;
                    cp_async16(bd + (uint32_t)(n * (BSTR * 2) + kc * 16),
                               &g_Wht[(size_t)n * NN + jn + kc * 8]);
                }
            }
            if (t < 64) cp_async16(cd + (uint32_t)t * 16, &g_colc[jn + t]);
            cp_commit();
            cp_wait1();   // B(tt)/colc(tt) complete; tt+1 in flight
        } else {
            cp_wait0();
        }

        // 3. visibility of B(tt)/colc(tt)
        __syncthreads();

        // 4. w-gen: registers(adj) + smem consts -> fp16 A[128][64]
        {
            const float4* cl = (const float4*)(smem + SM_COLC + buf * 1024);
            float4 cc0 = cl[2 * lane];
            float4 cc1 = cl[2 * lane + 1];
            const float4* rw = (const float4*)(smem + SM_ROWC) + wrow0;
            __half2* adst = (__half2*)(smem + SM_A) + lane;
#pragma unroll
            for (int r = 0; r < 16; r++) {
                float4 rc = rw[r];                 // LDS broadcast
                int2 a2 = av[r];
                float w0 = ((rc.x + cc0.x) > 0.f) ? rc.y * cc0.y : rc.z * cc0.z;
                float w1 = ((rc.x + cc1.x) > 0.f) ? rc.y * cc1.y : rc.z * cc1.z;
                w0 = a2.x ? w0 : 0.f;
                w1 = a2.y ? w1 : 0.f;
                adst[(wrow0 + r) * (ASTR / 2)] = __floats2half2_rn(w0, w1);
            }
        }

        // 5. stream adj(tt+1) into registers (flies over MMA + barriers)
        if (tt + 1 < NTILES) {
            int jn = j0 + BK;
#pragma unroll
            for (int r = 0; r < 16; r++)
                av[r] = __ldcs((const int2*)(aptr + (size_t)r * NN + jn));
        }

        // 6. A visible
        __syncthreads();

        // 7. MMA: 4 k-steps x (2 m-tiles x 5 n-tiles)
        const uint32_t* Bs32 = (const uint32_t*)(smem + SM_B + buf * (NB * BSTR * 2));
#pragma unroll
        for (int kt = 0; kt < 4; kt++) {
            int kb = kt * 16 + 2 * tig;          // half index (even)
            uint32_t a0[4], a1[4];
            {
                int r0 = mb + g;
                a0[0] = As32[r0 * (ASTR / 2) + (kb >> 1)];
                a0[1] = As32[(r0 + 8) * (ASTR / 2) + (kb >> 1)];
                a0[2] = As32[r0 * (ASTR / 2) + ((kb + 8) >> 1)];
                a0[3] = As32[(r0 + 8) * (ASTR / 2) + ((kb + 8) >> 1)];
                int r1 = mb + 16 + g;
                a1[0] = As32[r1 * (ASTR / 2) + (kb >> 1)];
                a1[1] = As32[(r1 + 8) * (ASTR / 2) + (kb >> 1)];
                a1[2] = As32[r1 * (ASTR / 2) + ((kb + 8) >> 1)];
                a1[3] = As32[(r1 + 8) * (ASTR / 2) + ((kb + 8) >> 1)];
            }
#pragma unroll
            for (int nt = 0; nt < 5; nt++) {
                int n = nb + nt * 8 + g;
                uint32_t b0 = Bs32[n * (BSTR / 2) + (kb >> 1)];
                uint32_t b1 = Bs32[n * (BSTR / 2) + ((kb + 8) >> 1)];
                asm volatile(
                    "mma.sync.aligned.m16n8k16.row.col.f32.f16.f16.f32 "
                    "{%0,%1,%2,%3}, {%4,%5,%6,%7}, {%8,%9}, {%0,%1,%2,%3};\n"
                    : "+f"(acc[0][nt][0]), "+f"(acc[0][nt][1]),
                      "+f"(acc[0][nt][2]), "+f"(acc[0][nt][3])
                    : "r"(a0[0]), "r"(a0[1]), "r"(a0[2]), "r"(a0[3]),
                      "r"(b0), "r"(b1));
                asm volatile(
                    "mma.sync.aligned.m16n8k16.row.col.f32.f16.f16.f32 "
                    "{%0,%1,%2,%3}, {%4,%5,%6,%7}, {%8,%9}, {%0,%1,%2,%3};\n"
                    : "+f"(acc[1][nt][0]), "+f"(acc[1][nt][1]),
                      "+f"(acc[1][nt][2]), "+f"(acc[1][nt][3])
                    : "r"(a1[0]), "r"(a1[1]), "r"(a1[2]), "r"(a1[3]),
                      "r"(b0), "r"(b1));
            }
        }
    }

    // ---- write partials: nums (cols 0..63) + den (logical col 64)
    float* pp = &g_part[((size_t)split * NN + i0) * PART_STRIDE];
#pragma unroll
    for (int m = 0; m < 2; m++) {
        int r0 = mb + m * 16 + g, r1 = r0 + 8;
#pragma unroll
        for (int nt = 0; nt < 5; nt++) {
            int nb2 = nb + nt * 8 + 2 * tig;
            if (nb2 < 64) {
                pp[(size_t)r0 * PART_STRIDE + nb2] = acc[m][nt][0];
                pp[(size_t)r1 * PART_STRIDE + nb2] = acc[m][nt][2];
            }
            if (nb2 + 1 < 64) {
                pp[(size_t)r0 * PART_STRIDE + nb2 + 1] = acc[m][nt][1];
                pp[(size_t)r1 * PART_STRIDE + nb2 + 1] = acc[m][nt][3];
            }
        }
        if (nb == 40 && tig == 0) {    // col 64 = 40 + 3*8 + 0
            pp[(size_t)r0 * PART_STRIDE + 64] = acc[m][3][0];
            pp[(size_t)r1 * PART_STRIDE + 64] = acc[m][3][2];
        }
    }
}

// ---------------------------------------------------------------------------
// Kernel 5: reduce partials across splits + elu (float4 per thread).
// ---------------------------------------------------------------------------
__global__ __launch_bounds__(256) void k_reduce(float* __restrict__ out)
{
    int idx = blockIdx.x * 256 + threadIdx.x;   // 0 .. NN*16
    int i = idx >> 4;
    int c4 = (idx & 15) * 4;

    float4 num = make_float4(0.f, 0.f, 0.f, 0.f);
    float den = 0.f;
#pragma unroll
    for (int s = 0; s < NSPLIT; s++) {
        const float* pp = &g_part[((size_t)s * NN + i) * PART_STRIDE];
        float4 v = *(const float4*)(pp + c4);
        num.x += v.x; num.y += v.y; num.z += v.z; num.w += v.w;
        den += pp[64];
    }
    float4 r;
    r.x = elu_f(num.x / den);
    r.y = elu_f(num.y / den);
    r.z = elu_f(num.z / den);
    r.w = elu_f(num.w / den);
    *(float4*)&out[(size_t)i * FOUT + c4] = r;
}

// ---------------------------------------------------------------------------
extern "C" void kernel_launch(void* const* d_in, const int* in_sizes, int n_in,
                              void* d_out, int out_size)
{
    const float* h   = (const float*)d_in[0];
    const int*   adj = (const int*)d_in[1];
    const float* W   = (const float*)d_in[2];
    const float* a   = (const float*)d_in[3];
    float* out = (float*)d_out;

    cudaFuncSetAttribute(k_gat, cudaFuncAttributeMaxDynamicSharedMemorySize,
                         SMEM_TOTAL);

    k_gemm_wh<<<NN / 16, 256>>>(h, W);
    k_fvec<<<NN / 256, 256>>>(a);
    k_consts<<<NN / 256, 256>>>();
    k_gat<<<(NN / BM) * NSPLIT, 256, SMEM_TOTAL>>>(adj);
    k_reduce<<<NN * 16 / 256, 256>>>(out);
}